// round 1
// baseline (speedup 1.0000x reference)
#include <cuda_runtime.h>
#include <math.h>

// ---------------------------------------------------------------------------
// Swin stage: B=64, H=W=56, D=128, WS=7, NH=4, 2 layers (layer 1 shifted),
// then 2x2 patch merge + LN + Linear(512->256).
// Round 0: fp32 SIMT baseline. GEMMs: 64x64x16 tiles, 256 thr, 4x4 microtile.
// ---------------------------------------------------------------------------

#define TOK 200704          // 64*56*56
#define DSTOK 50176         // 64*28*28

__device__ float g_x  [(size_t)TOK * 128];
__device__ float g_h  [(size_t)TOK * 128];
__device__ float g_qkv[(size_t)TOK * 384];
__device__ float g_o  [(size_t)TOK * 128];
__device__ float g_hid[(size_t)TOK * 512];
__device__ float g_ds [(size_t)DSTOK * 512];

// ------------------------------ LayerNorm (D=128), one warp per token -------
__global__ void __launch_bounds__(256)
ln128_kernel(const float* __restrict__ in, float* __restrict__ out,
             const float* __restrict__ g, const float* __restrict__ b)
{
    int warp = (blockIdx.x * blockDim.x + threadIdx.x) >> 5;
    int lane = threadIdx.x & 31;
    const float4 v = ((const float4*)(in + (size_t)warp * 128))[lane];
    float s = v.x + v.y + v.z + v.w;
#pragma unroll
    for (int o = 16; o; o >>= 1) s += __shfl_xor_sync(0xffffffffu, s, o);
    float mean = s * (1.0f / 128.0f);
    float dx = v.x - mean, dy = v.y - mean, dz = v.z - mean, dw = v.w - mean;
    float q = dx * dx + dy * dy + dz * dz + dw * dw;
#pragma unroll
    for (int o = 16; o; o >>= 1) q += __shfl_xor_sync(0xffffffffu, q, o);
    float rstd = rsqrtf(q * (1.0f / 128.0f) + 1e-5f);
    float4 gg = ((const float4*)g)[lane];
    float4 bb = ((const float4*)b)[lane];
    float4 r;
    r.x = dx * rstd * gg.x + bb.x;
    r.y = dy * rstd * gg.y + bb.y;
    r.z = dz * rstd * gg.z + bb.z;
    r.w = dw * rstd * gg.w + bb.w;
    ((float4*)(out + (size_t)warp * 128))[lane] = r;
}

// ------------------------------ GEMM: C[M,N] = A[M,K] @ W[K,N] (+bias)(+gelu)(+res)
__device__ __forceinline__ float gelu_tanh(float v)
{
    float u = 0.7978845608028654f * (v + 0.044715f * v * v * v);
    return 0.5f * v * (1.0f + tanhf(u));
}

template <bool GELU, bool RES>
__global__ void __launch_bounds__(256)
gemm64_kernel(const float* __restrict__ A, const float* __restrict__ W,
              const float* __restrict__ bias, const float* __restrict__ R,
              float* __restrict__ C, int N, int K)
{
    __shared__ float As[16][64];
    __shared__ float Bs[16][64];
    const int tid = threadIdx.x;
    const int tx = tid & 15, ty = tid >> 4;
    const int rowBase = blockIdx.y << 6;
    const int colBase = blockIdx.x << 6;
    const int am = tid >> 2, ak = (tid & 3) << 2;
    const int bk = tid >> 4, bn = (tid & 15) << 2;
    const float* Ap = A + (size_t)(rowBase + am) * K + ak;
    const float* Wp = W + (size_t)bk * N + colBase + bn;

    float acc[4][4] = {};
    for (int k0 = 0; k0 < K; k0 += 16) {
        float4 av = *(const float4*)(Ap + k0);
        float4 bv = *(const float4*)(Wp + (size_t)k0 * N);
        As[ak + 0][am] = av.x; As[ak + 1][am] = av.y;
        As[ak + 2][am] = av.z; As[ak + 3][am] = av.w;
        *(float4*)&Bs[bk][bn] = bv;
        __syncthreads();
#pragma unroll
        for (int kk = 0; kk < 16; kk++) {
            float4 a = *(const float4*)&As[kk][ty << 2];
            float4 b = *(const float4*)&Bs[kk][tx << 2];
            acc[0][0] += a.x * b.x; acc[0][1] += a.x * b.y; acc[0][2] += a.x * b.z; acc[0][3] += a.x * b.w;
            acc[1][0] += a.y * b.x; acc[1][1] += a.y * b.y; acc[1][2] += a.y * b.z; acc[1][3] += a.y * b.w;
            acc[2][0] += a.z * b.x; acc[2][1] += a.z * b.y; acc[2][2] += a.z * b.z; acc[2][3] += a.z * b.w;
            acc[3][0] += a.w * b.x; acc[3][1] += a.w * b.y; acc[3][2] += a.w * b.z; acc[3][3] += a.w * b.w;
        }
        __syncthreads();
    }

#pragma unroll
    for (int i = 0; i < 4; i++) {
        size_t row = (size_t)rowBase + (ty << 2) + i;
        size_t off = row * N + colBase + (tx << 2);
        float4 out;
        float* po = &out.x;
#pragma unroll
        for (int j = 0; j < 4; j++) {
            float v = acc[i][j];
            if (bias) v += bias[colBase + (tx << 2) + j];
            if (GELU) v = gelu_tanh(v);
            po[j] = v;
        }
        if (RES) {
            float4 r = *(const float4*)(R + off);
            out.x += r.x; out.y += r.y; out.z += r.z; out.w += r.w;
        }
        *(float4*)(C + off) = out;
    }
}

// ------------------------------ Window attention: one block per (b,window,head)
__global__ void __launch_bounds__(128)
attn_kernel(const float* __restrict__ qkv, float* __restrict__ o,
            int shift, int use_mask)
{
    __shared__ float qs[49][33], ks[49][33], vs[49][33];
    __shared__ float sc[49][49];
    __shared__ int   tok[49];
    __shared__ int   regn[49];

    const int tid  = threadIdx.x;
    const int head = blockIdx.y;
    const int bg   = blockIdx.x;
    const int b    = bg >> 6;   // /64 windows
    const int g    = bg & 63;
    const int gy   = g >> 3, gx = g & 7;

    if (tid < 49) {
        int wy = tid / 7, wx = tid - (tid / 7) * 7;
        int ph = gy * 7 + wy, pw = gx * 7 + wx;      // partition (shifted-img) coord
        int hh = ph + shift; if (hh >= 56) hh -= 56; // original-image coord
        int ww = pw + shift; if (ww >= 56) ww -= 56;
        tok[tid] = b * 3136 + hh * 56 + ww;
        int rh = (ph < 49) ? 0 : ((ph < 53) ? 1 : 2);
        int rw = (pw < 49) ? 0 : ((pw < 53) ? 1 : 2);
        regn[tid] = rh * 3 + rw;
    }
    __syncthreads();

    // load q,k,v tiles [49,32]
    for (int i = tid; i < 49 * 8; i += 128) {
        int r = i >> 3, c4 = (i & 7) << 2;
        const float* base = qkv + (size_t)tok[r] * 384 + head * 32 + c4;
        float4 q4 = *(const float4*)(base);
        float4 k4 = *(const float4*)(base + 128);
        float4 v4 = *(const float4*)(base + 256);
        qs[r][c4] = q4.x; qs[r][c4 + 1] = q4.y; qs[r][c4 + 2] = q4.z; qs[r][c4 + 3] = q4.w;
        ks[r][c4] = k4.x; ks[r][c4 + 1] = k4.y; ks[r][c4 + 2] = k4.z; ks[r][c4 + 3] = k4.w;
        vs[r][c4] = v4.x; vs[r][c4 + 1] = v4.y; vs[r][c4 + 2] = v4.z; vs[r][c4 + 3] = v4.w;
    }
    __syncthreads();

    // scores
    const float scale = 0.17677669529663689f; // 1/sqrt(32)
    for (int e = tid; e < 2401; e += 128) {
        int i = e / 49, j = e - i * 49;
        float s = 0.f;
#pragma unroll
        for (int c = 0; c < 32; c++) s += qs[i][c] * ks[j][c];
        s *= scale;
        if (use_mask && (regn[i] != regn[j])) s -= 100.f;
        sc[i][j] = s;
    }
    __syncthreads();

    // softmax: one thread per row
    if (tid < 49) {
        float m = -1e30f;
        for (int j = 0; j < 49; j++) m = fmaxf(m, sc[tid][j]);
        float sum = 0.f;
        for (int j = 0; j < 49; j++) {
            float e = __expf(sc[tid][j] - m);
            sc[tid][j] = e; sum += e;
        }
        float inv = 1.0f / sum;
        for (int j = 0; j < 49; j++) sc[tid][j] *= inv;
    }
    __syncthreads();

    // o = attn @ v
    for (int e = tid; e < 49 * 32; e += 128) {
        int i = e >> 5, c = e & 31;
        float s = 0.f;
#pragma unroll 7
        for (int j = 0; j < 49; j++) s += sc[i][j] * vs[j][c];
        o[(size_t)tok[i] * 128 + head * 32 + c] = s;
    }
}

// ------------------------------ 2x2 patch merge + LN(512), one warp per out-token
__global__ void __launch_bounds__(256)
merge_ln_kernel(const float* __restrict__ x, float* __restrict__ y,
                const float* __restrict__ g, const float* __restrict__ b)
{
    int warp = (blockIdx.x * blockDim.x + threadIdx.x) >> 5;
    int lane = threadIdx.x & 31;
    int bI = warp / 784;
    int r  = warp - bI * 784;
    int i  = r / 28;
    int j  = r - i * 28;
    int grp = lane >> 3;               // channel/128
    int hh  = grp >> 1, ww = grp & 1;
    int d0  = (lane & 7) << 4;         // offset within 128
    const float* src =
        x + (((size_t)(bI * 56 + 2 * i + hh)) * 56 + (2 * j + ww)) * 128 + d0;

    float v[16];
#pragma unroll
    for (int t = 0; t < 4; t++) {
        float4 f = ((const float4*)src)[t];
        v[t * 4 + 0] = f.x; v[t * 4 + 1] = f.y; v[t * 4 + 2] = f.z; v[t * 4 + 3] = f.w;
    }
    float s = 0.f;
#pragma unroll
    for (int t = 0; t < 16; t++) s += v[t];
#pragma unroll
    for (int o = 16; o; o >>= 1) s += __shfl_xor_sync(0xffffffffu, s, o);
    float mean = s * (1.0f / 512.0f);
    float q = 0.f;
#pragma unroll
    for (int t = 0; t < 16; t++) { float d = v[t] - mean; q += d * d; }
#pragma unroll
    for (int o = 16; o; o >>= 1) q += __shfl_xor_sync(0xffffffffu, q, o);
    float rstd = rsqrtf(q * (1.0f / 512.0f) + 1e-5f);

    int c0 = lane << 4;
    float* dst = y + (size_t)warp * 512 + c0;
#pragma unroll
    for (int t = 0; t < 4; t++) {
        float4 gg = ((const float4*)(g + c0))[t];
        float4 bb = ((const float4*)(b + c0))[t];
        float4 out;
        out.x = (v[t * 4 + 0] - mean) * rstd * gg.x + bb.x;
        out.y = (v[t * 4 + 1] - mean) * rstd * gg.y + bb.y;
        out.z = (v[t * 4 + 2] - mean) * rstd * gg.z + bb.z;
        out.w = (v[t * 4 + 3] - mean) * rstd * gg.w + bb.w;
        ((float4*)dst)[t] = out;
    }
}

// ---------------------------------------------------------------------------
extern "C" void kernel_launch(void* const* d_in, const int* in_sizes, int n_in,
                              void* d_out, int out_size)
{
    const float* x       = (const float*)d_in[0];
    const float* ln1_g   = (const float*)d_in[1];
    const float* ln1_b   = (const float*)d_in[2];
    const float* qkv_w   = (const float*)d_in[3];
    const float* qkv_b   = (const float*)d_in[4];
    const float* proj_w  = (const float*)d_in[5];
    const float* proj_b  = (const float*)d_in[6];
    const float* ln2_g   = (const float*)d_in[7];
    const float* ln2_b   = (const float*)d_in[8];
    const float* mlp_w1  = (const float*)d_in[9];
    const float* mlp_b1  = (const float*)d_in[10];
    const float* mlp_w2  = (const float*)d_in[11];
    const float* mlp_b2  = (const float*)d_in[12];
    const float* dsn_g   = (const float*)d_in[13];
    const float* dsn_b   = (const float*)d_in[14];
    const float* ds_w    = (const float*)d_in[15];
    float* out           = (float*)d_out;

    float *gx, *gh, *gq, *go, *ghid, *gds;
    cudaGetSymbolAddress((void**)&gx,   g_x);
    cudaGetSymbolAddress((void**)&gh,   g_h);
    cudaGetSymbolAddress((void**)&gq,   g_qkv);
    cudaGetSymbolAddress((void**)&go,   g_o);
    cudaGetSymbolAddress((void**)&ghid, g_hid);
    cudaGetSymbolAddress((void**)&gds,  g_ds);

    const int lnBlocks = TOK / 8;       // 25088 (warp per token, 8 warps/block)
    const dim3 attnGrid(4096, 4);       // (B*G, heads)

    for (int layer = 0; layer < 2; layer++) {
        const float* res_in = (layer == 0) ? x : gx;  // residual stream source
        int shift   = (layer == 1) ? 3 : 0;
        int useMask = (layer == 1) ? 1 : 0;

        // LN1
        ln128_kernel<<<lnBlocks, 256>>>(res_in, gh,
                                        ln1_g + layer * 128, ln1_b + layer * 128);
        // QKV: [TOK,128] @ [128,384]
        gemm64_kernel<false, false><<<dim3(384 / 64, TOK / 64), 256>>>(
            gh, qkv_w + (size_t)layer * 128 * 384, qkv_b + layer * 384,
            nullptr, gq, 384, 128);
        // Window attention
        attn_kernel<<<attnGrid, 128>>>(gq, go, shift, useMask);
        // Proj + residual: x = res + o @ Wp
        gemm64_kernel<false, true><<<dim3(2, TOK / 64), 256>>>(
            go, proj_w + (size_t)layer * 128 * 128, proj_b + layer * 128,
            res_in, gx, 128, 128);
        // LN2
        ln128_kernel<<<lnBlocks, 256>>>(gx, gh,
                                        ln2_g + layer * 128, ln2_b + layer * 128);
        // MLP1 + GELU: [TOK,128] @ [128,512]
        gemm64_kernel<true, false><<<dim3(8, TOK / 64), 256>>>(
            gh, mlp_w1 + (size_t)layer * 128 * 512, mlp_b1 + layer * 512,
            nullptr, ghid, 512, 128);
        // MLP2 + residual: x = x + hid @ W2
        gemm64_kernel<false, true><<<dim3(2, TOK / 64), 256>>>(
            ghid, mlp_w2 + (size_t)layer * 512 * 128, mlp_b2 + layer * 128,
            gx, gx, 128, 512);
    }

    // Downsample: 2x2 merge + LN(512) -> [DSTOK,512], then @ [512,256]
    merge_ln_kernel<<<DSTOK / 8, 256>>>(gx, gds, dsn_g, dsn_b);
    gemm64_kernel<false, false><<<dim3(256 / 64, DSTOK / 64), 256>>>(
        gds, ds_w, nullptr, nullptr, out, 256, 512);
}

// round 3
// speedup vs baseline: 1.9268x; 1.9268x over previous
#include <cuda_runtime.h>
#include <cstdint>
#include <math.h>

// ---------------------------------------------------------------------------
// Swin stage on GB300 (compute_103 target: tcgen05 unavailable -> mma.sync tf32).
// B=64, H=W=56, D=128, WS=7, NH=4, 2 layers (layer 1 shifted), merge+LN+Linear.
// ---------------------------------------------------------------------------

#define TOK 200704          // 64*56*56
#define DSTOK 50176         // 64*28*28

__device__ float g_x  [(size_t)TOK * 128];
__device__ float g_h  [(size_t)TOK * 128];
__device__ float g_qkv[(size_t)TOK * 384];
__device__ float g_o  [(size_t)TOK * 128];
__device__ float g_hid[(size_t)TOK * 512];
__device__ float g_ds [(size_t)DSTOK * 512];
__device__ float g_wt [524288];   // transposed weights [N,K] K-major

__device__ __forceinline__ uint32_t f2tf32(float f) {
    uint32_t u; asm("cvt.rna.tf32.f32 %0, %1;" : "=r"(u) : "f"(f)); return u;
}

#define MMA_TF32(d, a, b) \
    asm volatile("mma.sync.aligned.m16n8k8.row.col.f32.tf32.tf32.f32 " \
        "{%0,%1,%2,%3}, {%4,%5,%6,%7}, {%8,%9}, {%0,%1,%2,%3};" \
        : "+f"((d)[0]), "+f"((d)[1]), "+f"((d)[2]), "+f"((d)[3]) \
        : "r"((a)[0]), "r"((a)[1]), "r"((a)[2]), "r"((a)[3]), \
          "r"((b)[0]), "r"((b)[1]))

__device__ __forceinline__ float gelu_tanh(float v) {
    float u = 0.7978845608028654f * (v + 0.044715f * v * v * v);
    return 0.5f * v * (1.0f + tanhf(u));
}

// ------------------------------ tf32 mma GEMM --------------------------------
// C[M,N] = A[M,K] @ WT[N,K]^T (+bias)(+gelu)(+residual)
// 128x128 block, BK=32, 8 warps (4M x 2N), warp tile 32x64 = 2x8 m16n8k8.
template <bool GELU, bool RES>
__global__ void __launch_bounds__(256, 2)
gemm_mma(const float* __restrict__ A, const float* __restrict__ WT,
         const float* __restrict__ bias, const float* __restrict__ R,
         float* __restrict__ C, int N, int K)
{
    __shared__ float As[128][36];
    __shared__ float Bs[128][36];
    const int tid  = threadIdx.x;
    const int wid  = tid >> 5, lane = tid & 31;
    const int gID  = lane >> 2, tig = lane & 3;
    const int warpM = wid & 3, warpN = wid >> 2;
    const int rowBase = blockIdx.y << 7;
    const int colBase = blockIdx.x << 7;
    const int lr = tid >> 3;            // load row base (0..31), +32*i
    const int lc = (tid & 7) << 2;      // load col (0,4,...,28)

    float d[2][8][4];
#pragma unroll
    for (int mi = 0; mi < 2; mi++)
#pragma unroll
        for (int ni = 0; ni < 8; ni++)
#pragma unroll
            for (int e = 0; e < 4; e++) d[mi][ni][e] = 0.f;

    const int rA = warpM * 32 + gID;
    const int cB = warpN * 64 + gID;

    for (int k0 = 0; k0 < K; k0 += 32) {
#pragma unroll
        for (int i = 0; i < 4; i++) {
            int r = lr + (i << 5);
            float4 va = *(const float4*)(A  + (size_t)(rowBase + r) * K + k0 + lc);
            float4 vb = *(const float4*)(WT + (size_t)(colBase + r) * K + k0 + lc);
            float4 ta, tb;
            ta.x = __uint_as_float(f2tf32(va.x)); ta.y = __uint_as_float(f2tf32(va.y));
            ta.z = __uint_as_float(f2tf32(va.z)); ta.w = __uint_as_float(f2tf32(va.w));
            tb.x = __uint_as_float(f2tf32(vb.x)); tb.y = __uint_as_float(f2tf32(vb.y));
            tb.z = __uint_as_float(f2tf32(vb.z)); tb.w = __uint_as_float(f2tf32(vb.w));
            *(float4*)&As[r][lc] = ta;
            *(float4*)&Bs[r][lc] = tb;
        }
        __syncthreads();
#pragma unroll
        for (int ks = 0; ks < 4; ks++) {
            const int kk = ks << 3;
            uint32_t af[2][4], bf[8][2];
#pragma unroll
            for (int mi = 0; mi < 2; mi++) {
                af[mi][0] = __float_as_uint(As[rA + mi * 16][kk + tig]);
                af[mi][1] = __float_as_uint(As[rA + mi * 16 + 8][kk + tig]);
                af[mi][2] = __float_as_uint(As[rA + mi * 16][kk + tig + 4]);
                af[mi][3] = __float_as_uint(As[rA + mi * 16 + 8][kk + tig + 4]);
            }
#pragma unroll
            for (int ni = 0; ni < 8; ni++) {
                bf[ni][0] = __float_as_uint(Bs[cB + ni * 8][kk + tig]);
                bf[ni][1] = __float_as_uint(Bs[cB + ni * 8][kk + tig + 4]);
            }
#pragma unroll
            for (int mi = 0; mi < 2; mi++)
#pragma unroll
                for (int ni = 0; ni < 8; ni++)
                    MMA_TF32(d[mi][ni], af[mi], bf[ni]);
        }
        __syncthreads();
    }

    // epilogue: each (mi,ni) tile -> rows (row0, row0+8), cols col0..col0+1
    const int row0 = rowBase + warpM * 32 + gID;
    const int colW = colBase + warpN * 64 + (tig << 1);
#pragma unroll
    for (int ni = 0; ni < 8; ni++) {
        const int col = colW + ni * 8;
        float bx = 0.f, by = 0.f;
        if (bias) { bx = bias[col]; by = bias[col + 1]; }
#pragma unroll
        for (int mi = 0; mi < 2; mi++) {
#pragma unroll
            for (int half = 0; half < 2; half++) {
                int r = row0 + mi * 16 + half * 8;
                float vx = d[mi][ni][half * 2 + 0] + bx;
                float vy = d[mi][ni][half * 2 + 1] + by;
                if (GELU) { vx = gelu_tanh(vx); vy = gelu_tanh(vy); }
                size_t off = (size_t)r * N + col;
                if (RES) {
                    float2 rr = *(const float2*)(R + off);
                    vx += rr.x; vy += rr.y;
                }
                float2 o = { vx, vy };
                *(float2*)(C + off) = o;
            }
        }
    }
}

// ------------------------------ weight transpose: out[N,K] = in[K,N]^T ------
__global__ void transpose_k(const float* __restrict__ in, float* __restrict__ out,
                            int K, int N)
{
    int i = blockIdx.x * 256 + threadIdx.x;
    if (i < K * N) {
        int n = i / K, k = i - n * K;
        out[i] = in[k * N + n];
    }
}

// ------------------------------ LayerNorm (D=128), one warp per token -------
__global__ void __launch_bounds__(256)
ln128_kernel(const float* __restrict__ in, float* __restrict__ out,
             const float* __restrict__ g, const float* __restrict__ b)
{
    int warp = (blockIdx.x * blockDim.x + threadIdx.x) >> 5;
    int lane = threadIdx.x & 31;
    const float4 v = ((const float4*)(in + (size_t)warp * 128))[lane];
    float s = v.x + v.y + v.z + v.w;
#pragma unroll
    for (int o = 16; o; o >>= 1) s += __shfl_xor_sync(0xffffffffu, s, o);
    float mean = s * (1.0f / 128.0f);
    float dx = v.x - mean, dy = v.y - mean, dz = v.z - mean, dw = v.w - mean;
    float q = dx * dx + dy * dy + dz * dz + dw * dw;
#pragma unroll
    for (int o = 16; o; o >>= 1) q += __shfl_xor_sync(0xffffffffu, q, o);
    float rstd = rsqrtf(q * (1.0f / 128.0f) + 1e-5f);
    float4 gg = ((const float4*)g)[lane];
    float4 bb = ((const float4*)b)[lane];
    float4 r;
    r.x = dx * rstd * gg.x + bb.x;
    r.y = dy * rstd * gg.y + bb.y;
    r.z = dz * rstd * gg.z + bb.z;
    r.w = dw * rstd * gg.w + bb.w;
    ((float4*)(out + (size_t)warp * 128))[lane] = r;
}

// ------------------------------ Window attention ----------------------------
__global__ void __launch_bounds__(128)
attn_kernel(const float* __restrict__ qkv, float* __restrict__ o,
            int shift, int use_mask)
{
    __shared__ float qs[49][33], ks[49][33], vs[49][33];
    __shared__ float sc[49][49];
    __shared__ int   tok[49];
    __shared__ int   regn[49];

    const int tid  = threadIdx.x;
    const int head = blockIdx.y;
    const int bg   = blockIdx.x;
    const int b    = bg >> 6;
    const int g    = bg & 63;
    const int gy   = g >> 3, gx = g & 7;

    if (tid < 49) {
        int wy = tid / 7, wx = tid - (tid / 7) * 7;
        int ph = gy * 7 + wy, pw = gx * 7 + wx;
        int hh = ph + shift; if (hh >= 56) hh -= 56;
        int ww = pw + shift; if (ww >= 56) ww -= 56;
        tok[tid] = b * 3136 + hh * 56 + ww;
        int rh = (ph < 49) ? 0 : ((ph < 53) ? 1 : 2);
        int rw = (pw < 49) ? 0 : ((pw < 53) ? 1 : 2);
        regn[tid] = rh * 3 + rw;
    }
    __syncthreads();

    for (int i = tid; i < 49 * 8; i += 128) {
        int r = i >> 3, c4 = (i & 7) << 2;
        const float* base = qkv + (size_t)tok[r] * 384 + head * 32 + c4;
        float4 q4 = *(const float4*)(base);
        float4 k4 = *(const float4*)(base + 128);
        float4 v4 = *(const float4*)(base + 256);
        qs[r][c4] = q4.x; qs[r][c4 + 1] = q4.y; qs[r][c4 + 2] = q4.z; qs[r][c4 + 3] = q4.w;
        ks[r][c4] = k4.x; ks[r][c4 + 1] = k4.y; ks[r][c4 + 2] = k4.z; ks[r][c4 + 3] = k4.w;
        vs[r][c4] = v4.x; vs[r][c4 + 1] = v4.y; vs[r][c4 + 2] = v4.z; vs[r][c4 + 3] = v4.w;
    }
    __syncthreads();

    const float scale = 0.17677669529663689f;
    for (int e = tid; e < 2401; e += 128) {
        int i = e / 49, j = e - i * 49;
        float s = 0.f;
#pragma unroll
        for (int c = 0; c < 32; c++) s += qs[i][c] * ks[j][c];
        s *= scale;
        if (use_mask && (regn[i] != regn[j])) s -= 100.f;
        sc[i][j] = s;
    }
    __syncthreads();

    if (tid < 49) {
        float m = -1e30f;
        for (int j = 0; j < 49; j++) m = fmaxf(m, sc[tid][j]);
        float sum = 0.f;
        for (int j = 0; j < 49; j++) {
            float e = __expf(sc[tid][j] - m);
            sc[tid][j] = e; sum += e;
        }
        float inv = 1.0f / sum;
        for (int j = 0; j < 49; j++) sc[tid][j] *= inv;
    }
    __syncthreads();

    for (int e = tid; e < 49 * 32; e += 128) {
        int i = e >> 5, c = e & 31;
        float s = 0.f;
#pragma unroll 7
        for (int j = 0; j < 49; j++) s += sc[i][j] * vs[j][c];
        o[(size_t)tok[i] * 128 + head * 32 + c] = s;
    }
}

// ------------------------------ 2x2 patch merge + LN(512) -------------------
__global__ void __launch_bounds__(256)
merge_ln_kernel(const float* __restrict__ x, float* __restrict__ y,
                const float* __restrict__ g, const float* __restrict__ b)
{
    int warp = (blockIdx.x * blockDim.x + threadIdx.x) >> 5;
    int lane = threadIdx.x & 31;
    int bI = warp / 784;
    int r  = warp - bI * 784;
    int i  = r / 28;
    int j  = r - i * 28;
    int grp = lane >> 3;
    int hh  = grp >> 1, ww = grp & 1;
    int d0  = (lane & 7) << 4;
    const float* src =
        x + (((size_t)(bI * 56 + 2 * i + hh)) * 56 + (2 * j + ww)) * 128 + d0;

    float v[16];
#pragma unroll
    for (int t = 0; t < 4; t++) {
        float4 f = ((const float4*)src)[t];
        v[t * 4 + 0] = f.x; v[t * 4 + 1] = f.y; v[t * 4 + 2] = f.z; v[t * 4 + 3] = f.w;
    }
    float s = 0.f;
#pragma unroll
    for (int t = 0; t < 16; t++) s += v[t];
#pragma unroll
    for (int o = 16; o; o >>= 1) s += __shfl_xor_sync(0xffffffffu, s, o);
    float mean = s * (1.0f / 512.0f);
    float q = 0.f;
#pragma unroll
    for (int t = 0; t < 16; t++) { float dd = v[t] - mean; q += dd * dd; }
#pragma unroll
    for (int o = 16; o; o >>= 1) q += __shfl_xor_sync(0xffffffffu, q, o);
    float rstd = rsqrtf(q * (1.0f / 512.0f) + 1e-5f);

    int c0 = lane << 4;
    float* dst = y + (size_t)warp * 512 + c0;
#pragma unroll
    for (int t = 0; t < 4; t++) {
        float4 gg = ((const float4*)(g + c0))[t];
        float4 bb = ((const float4*)(b + c0))[t];
        float4 out;
        out.x = (v[t * 4 + 0] - mean) * rstd * gg.x + bb.x;
        out.y = (v[t * 4 + 1] - mean) * rstd * gg.y + bb.y;
        out.z = (v[t * 4 + 2] - mean) * rstd * gg.z + bb.z;
        out.w = (v[t * 4 + 3] - mean) * rstd * gg.w + bb.w;
        ((float4*)dst)[t] = out;
    }
}

// ---------------------------------------------------------------------------
extern "C" void kernel_launch(void* const* d_in, const int* in_sizes, int n_in,
                              void* d_out, int out_size)
{
    const float* x       = (const float*)d_in[0];
    const float* ln1_g   = (const float*)d_in[1];
    const float* ln1_b   = (const float*)d_in[2];
    const float* qkv_w   = (const float*)d_in[3];
    const float* qkv_b   = (const float*)d_in[4];
    const float* proj_w  = (const float*)d_in[5];
    const float* proj_b  = (const float*)d_in[6];
    const float* ln2_g   = (const float*)d_in[7];
    const float* ln2_b   = (const float*)d_in[8];
    const float* mlp_w1  = (const float*)d_in[9];
    const float* mlp_b1  = (const float*)d_in[10];
    const float* mlp_w2  = (const float*)d_in[11];
    const float* mlp_b2  = (const float*)d_in[12];
    const float* dsn_g   = (const float*)d_in[13];
    const float* dsn_b   = (const float*)d_in[14];
    const float* ds_w    = (const float*)d_in[15];
    float* out           = (float*)d_out;

    float *gx, *gh, *gq, *go, *ghid, *gds, *gwt;
    cudaGetSymbolAddress((void**)&gx,   g_x);
    cudaGetSymbolAddress((void**)&gh,   g_h);
    cudaGetSymbolAddress((void**)&gq,   g_qkv);
    cudaGetSymbolAddress((void**)&go,   g_o);
    cudaGetSymbolAddress((void**)&ghid, g_hid);
    cudaGetSymbolAddress((void**)&gds,  g_ds);
    cudaGetSymbolAddress((void**)&gwt,  g_wt);

    // transpose all weights into [N,K] K-major
    // offsets: qkvT 0 (+l*49152) | projT 98304 (+l*16384) | mlp1T 131072 (+l*65536)
    //          mlp2T 262144 (+l*65536) | dsT 393216
    for (int l = 0; l < 2; l++) {
        transpose_k<<<(128 * 384 + 255) / 256, 256>>>(qkv_w  + (size_t)l * 128 * 384, gwt + 0      + l * 49152, 128, 384);
        transpose_k<<<(128 * 128 + 255) / 256, 256>>>(proj_w + (size_t)l * 128 * 128, gwt + 98304  + l * 16384, 128, 128);
        transpose_k<<<(128 * 512 + 255) / 256, 256>>>(mlp_w1 + (size_t)l * 128 * 512, gwt + 131072 + l * 65536, 128, 512);
        transpose_k<<<(512 * 128 + 255) / 256, 256>>>(mlp_w2 + (size_t)l * 512 * 128, gwt + 262144 + l * 65536, 512, 128);
    }
    transpose_k<<<(512 * 256 + 255) / 256, 256>>>(ds_w, gwt + 393216, 512, 256);

    const int lnBlocks = TOK / 8;
    const dim3 attnGrid(4096, 4);

    for (int layer = 0; layer < 2; layer++) {
        const float* res_in = (layer == 0) ? x : gx;
        int shift   = (layer == 1) ? 3 : 0;
        int useMask = (layer == 1) ? 1 : 0;

        ln128_kernel<<<lnBlocks, 256>>>(res_in, gh,
                                        ln1_g + layer * 128, ln1_b + layer * 128);
        gemm_mma<false, false><<<dim3(3, TOK / 128), 256>>>(
            gh, gwt + 0 + layer * 49152, qkv_b + layer * 384, nullptr, gq, 384, 128);
        attn_kernel<<<attnGrid, 128>>>(gq, go, shift, useMask);
        gemm_mma<false, true><<<dim3(1, TOK / 128), 256>>>(
            go, gwt + 98304 + layer * 16384, proj_b + layer * 128, res_in, gx, 128, 128);
        ln128_kernel<<<lnBlocks, 256>>>(gx, gh,
                                        ln2_g + layer * 128, ln2_b + layer * 128);
        gemm_mma<true, false><<<dim3(4, TOK / 128), 256>>>(
            gh, gwt + 131072 + layer * 65536, mlp_b1 + layer * 512, nullptr, ghid, 512, 128);
        gemm_mma<false, true><<<dim3(1, TOK / 128), 256>>>(
            ghid, gwt + 262144 + layer * 65536, mlp_b2 + layer * 128, gx, gx, 128, 512);
    }

    merge_ln_kernel<<<DSTOK / 8, 256>>>(gx, gds, dsn_g, dsn_b);
    gemm_mma<false, false><<<dim3(2, DSTOK / 128), 256>>>(
        gds, gwt + 393216, nullptr, nullptr, out, 256, 512);
}

// round 4
// speedup vs baseline: 2.1061x; 1.0931x over previous
#include <cuda_runtime.h>
#include <cstdint>
#include <math.h>

// ---------------------------------------------------------------------------
// Swin stage on GB300 (compute_103: mma.sync tf32 path).
// R4: cp.async double-buffered GEMM, tf32-preconverted weights, parallel softmax.
// ---------------------------------------------------------------------------

#define TOK 200704          // 64*56*56
#define DSTOK 50176         // 64*28*28

__device__ float g_x  [(size_t)TOK * 128];
__device__ float g_h  [(size_t)TOK * 128];
__device__ float g_qkv[(size_t)TOK * 384];
__device__ float g_o  [(size_t)TOK * 128];
__device__ float g_hid[(size_t)TOK * 512];
__device__ float g_ds [(size_t)DSTOK * 512];
__device__ float g_wt [524288];   // transposed weights [N,K] K-major, tf32-rounded

__device__ __forceinline__ uint32_t f2tf32(float f) {
    uint32_t u; asm("cvt.rna.tf32.f32 %0, %1;" : "=r"(u) : "f"(f)); return u;
}
__device__ __forceinline__ uint32_t smem_u32(const void* p) {
    uint32_t a;
    asm("{ .reg .u64 t; cvta.to.shared.u64 t, %1; cvt.u32.u64 %0, t; }" : "=r"(a) : "l"(p));
    return a;
}

#define CP_ASYNC16(dst, src) \
    asm volatile("cp.async.cg.shared.global [%0], [%1], 16;" :: "r"(dst), "l"(src))
#define CP_COMMIT() asm volatile("cp.async.commit_group;" ::: "memory")
#define CP_WAIT1()  asm volatile("cp.async.wait_group 1;" ::: "memory")
#define CP_WAIT0()  asm volatile("cp.async.wait_group 0;" ::: "memory")

#define MMA_TF32(d, a, b) \
    asm volatile("mma.sync.aligned.m16n8k8.row.col.f32.tf32.tf32.f32 " \
        "{%0,%1,%2,%3}, {%4,%5,%6,%7}, {%8,%9}, {%0,%1,%2,%3};" \
        : "+f"((d)[0]), "+f"((d)[1]), "+f"((d)[2]), "+f"((d)[3]) \
        : "r"((a)[0]), "r"((a)[1]), "r"((a)[2]), "r"((a)[3]), \
          "r"((b)[0]), "r"((b)[1]))

__device__ __forceinline__ float gelu_tanh(float v) {
    float u = 0.7978845608028654f * (v + 0.044715f * v * v * v);
    return 0.5f * v * (1.0f + tanhf(u));
}

// ------------------------------ tf32 mma GEMM, cp.async double-buffered ------
// C[M,N] = A[M,K] @ WT[N,K]^T (+bias)(+gelu)(+residual)
// 128x128 block, BK=32, 8 warps (4M x 2N). Stage = As[128][36] + Bs[128][36].
#define GSTAGE 4608               // floats per tile (128*36)
#define GEMM_SMEM (2 * 2 * GSTAGE * 4)   // 73728 bytes

template <bool GELU, bool RES>
__global__ void __launch_bounds__(256, 2)
gemm_mma(const float* __restrict__ A, const float* __restrict__ WT,
         const float* __restrict__ bias, const float* __restrict__ R,
         float* __restrict__ C, int N, int K)
{
    extern __shared__ float sm[];
    const uint32_t sm0 = smem_u32(sm);
    const int tid  = threadIdx.x;
    const int wid  = tid >> 5, lane = tid & 31;
    const int gID  = lane >> 2, tig = lane & 3;
    const int warpM = wid & 3, warpN = wid >> 2;
    const int rowBase = blockIdx.y << 7;
    const int colBase = blockIdx.x << 7;
    const int lr = tid >> 3;            // load row base (0..31), +32*i
    const int lc = (tid & 7) << 2;      // load col (0,4,...,28)

    const float* Ab  = A  + (size_t)(rowBase + lr) * K + lc;
    const float* Wb  = WT + (size_t)(colBase + lr) * K + lc;
    const uint32_t dstA = sm0 + (uint32_t)(lr * 36 + lc) * 4;
    const uint32_t dstB = dstA + GSTAGE * 4;

    float d[2][8][4];
#pragma unroll
    for (int mi = 0; mi < 2; mi++)
#pragma unroll
        for (int ni = 0; ni < 8; ni++)
#pragma unroll
            for (int e = 0; e < 4; e++) d[mi][ni][e] = 0.f;

    const int nch = K >> 5;

    // issue chunk into stage s
#define ISSUE(c_, s_) do {                                                   \
        const int k0_ = (c_) << 5;                                          \
        const uint32_t so_ = (uint32_t)(s_) * (2 * GSTAGE * 4);             \
        _Pragma("unroll")                                                    \
        for (int i_ = 0; i_ < 4; i_++) {                                     \
            CP_ASYNC16(dstA + so_ + i_ * (32 * 36 * 4),                      \
                       Ab + (size_t)(i_ << 5) * K + k0_);                    \
            CP_ASYNC16(dstB + so_ + i_ * (32 * 36 * 4),                      \
                       Wb + (size_t)(i_ << 5) * K + k0_);                    \
        }                                                                    \
        CP_COMMIT();                                                         \
    } while (0)

    ISSUE(0, 0);
    ISSUE(1, 1);

    const int rA = warpM * 32 + gID;
    const int cB = warpN * 64 + gID;

    for (int c = 0; c < nch; c++) {
        const int s = c & 1;
        if (c == nch - 1) { CP_WAIT0(); } else { CP_WAIT1(); }
        __syncthreads();
        const float* As = sm + s * (2 * GSTAGE);
        const float* Bs = As + GSTAGE;
#pragma unroll
        for (int ks = 0; ks < 4; ks++) {
            const int kk = ks << 3;
            uint32_t af[2][4], bf[8][2];
#pragma unroll
            for (int mi = 0; mi < 2; mi++) {
                af[mi][0] = f2tf32(As[(rA + mi * 16) * 36 + kk + tig]);
                af[mi][1] = f2tf32(As[(rA + mi * 16 + 8) * 36 + kk + tig]);
                af[mi][2] = f2tf32(As[(rA + mi * 16) * 36 + kk + tig + 4]);
                af[mi][3] = f2tf32(As[(rA + mi * 16 + 8) * 36 + kk + tig + 4]);
            }
#pragma unroll
            for (int ni = 0; ni < 8; ni++) {
                bf[ni][0] = __float_as_uint(Bs[(cB + ni * 8) * 36 + kk + tig]);
                bf[ni][1] = __float_as_uint(Bs[(cB + ni * 8) * 36 + kk + tig + 4]);
            }
#pragma unroll
            for (int mi = 0; mi < 2; mi++)
#pragma unroll
                for (int ni = 0; ni < 8; ni++)
                    MMA_TF32(d[mi][ni], af[mi], bf[ni]);
        }
        __syncthreads();
        if (c + 2 < nch) ISSUE(c + 2, s);
    }
#undef ISSUE

    // epilogue
    const int row0 = rowBase + warpM * 32 + gID;
    const int colW = colBase + warpN * 64 + (tig << 1);
#pragma unroll
    for (int ni = 0; ni < 8; ni++) {
        const int col = colW + ni * 8;
        float bx = 0.f, by = 0.f;
        if (bias) { bx = bias[col]; by = bias[col + 1]; }
#pragma unroll
        for (int mi = 0; mi < 2; mi++) {
#pragma unroll
            for (int half = 0; half < 2; half++) {
                int r = row0 + mi * 16 + half * 8;
                float vx = d[mi][ni][half * 2 + 0] + bx;
                float vy = d[mi][ni][half * 2 + 1] + by;
                if (GELU) { vx = gelu_tanh(vx); vy = gelu_tanh(vy); }
                size_t off = (size_t)r * N + col;
                if (RES) {
                    float2 rr = *(const float2*)(R + off);
                    vx += rr.x; vy += rr.y;
                }
                float2 o = { vx, vy };
                *(float2*)(C + off) = o;
            }
        }
    }
}

// ---------------- weight transpose + tf32 round: out[l][N,K] = in[l][K,N]^T --
__global__ void transpose_tf32(const float* __restrict__ in, float* __restrict__ out,
                               int K, int N, int perL)
{
    int i = blockIdx.x * 256 + threadIdx.x;
    int total = K * N;
    int l = i >= total ? 1 : 0;      // layer (grid sized to L*total when perL>0)
    int r = i - l * total;
    if (r < total && (perL || l == 0)) {
        int n = r / K, k = r - n * K;
        float v = in[(size_t)l * total + k * N + n];
        out[(size_t)l * perL + r] = __uint_as_float(f2tf32(v));
    }
}

// ------------------------------ LayerNorm (D=128), one warp per token -------
__global__ void __launch_bounds__(256)
ln128_kernel(const float* __restrict__ in, float* __restrict__ out,
             const float* __restrict__ g, const float* __restrict__ b)
{
    int warp = (blockIdx.x * blockDim.x + threadIdx.x) >> 5;
    int lane = threadIdx.x & 31;
    const float4 v = ((const float4*)(in + (size_t)warp * 128))[lane];
    float s = v.x + v.y + v.z + v.w;
#pragma unroll
    for (int o = 16; o; o >>= 1) s += __shfl_xor_sync(0xffffffffu, s, o);
    float mean = s * (1.0f / 128.0f);
    float dx = v.x - mean, dy = v.y - mean, dz = v.z - mean, dw = v.w - mean;
    float q = dx * dx + dy * dy + dz * dz + dw * dw;
#pragma unroll
    for (int o = 16; o; o >>= 1) q += __shfl_xor_sync(0xffffffffu, q, o);
    float rstd = rsqrtf(q * (1.0f / 128.0f) + 1e-5f);
    float4 gg = ((const float4*)g)[lane];
    float4 bb = ((const float4*)b)[lane];
    float4 r;
    r.x = dx * rstd * gg.x + bb.x;
    r.y = dy * rstd * gg.y + bb.y;
    r.z = dz * rstd * gg.z + bb.z;
    r.w = dw * rstd * gg.w + bb.w;
    ((float4*)(out + (size_t)warp * 128))[lane] = r;
}

// ------------------------------ Window attention ----------------------------
__global__ void __launch_bounds__(128)
attn_kernel(const float* __restrict__ qkv, float* __restrict__ o,
            int shift, int use_mask)
{
    __shared__ float qs[49][33], ks[49][33], vs[49][33];
    __shared__ float sc[49][49];
    __shared__ int   tok[49];
    __shared__ int   regn[49];

    const int tid  = threadIdx.x;
    const int wid  = tid >> 5, lane = tid & 31;
    const int head = blockIdx.y;
    const int bg   = blockIdx.x;
    const int b    = bg >> 6;
    const int g    = bg & 63;
    const int gy   = g >> 3, gx = g & 7;

    if (tid < 49) {
        int wy = tid / 7, wx = tid - (tid / 7) * 7;
        int ph = gy * 7 + wy, pw = gx * 7 + wx;
        int hh = ph + shift; if (hh >= 56) hh -= 56;
        int ww = pw + shift; if (ww >= 56) ww -= 56;
        tok[tid] = b * 3136 + hh * 56 + ww;
        int rh = (ph < 49) ? 0 : ((ph < 53) ? 1 : 2);
        int rw = (pw < 49) ? 0 : ((pw < 53) ? 1 : 2);
        regn[tid] = rh * 3 + rw;
    }
    __syncthreads();

    for (int i = tid; i < 49 * 8; i += 128) {
        int r = i >> 3, c4 = (i & 7) << 2;
        const float* base = qkv + (size_t)tok[r] * 384 + head * 32 + c4;
        float4 q4 = *(const float4*)(base);
        float4 k4 = *(const float4*)(base + 128);
        float4 v4 = *(const float4*)(base + 256);
        qs[r][c4] = q4.x; qs[r][c4 + 1] = q4.y; qs[r][c4 + 2] = q4.z; qs[r][c4 + 3] = q4.w;
        ks[r][c4] = k4.x; ks[r][c4 + 1] = k4.y; ks[r][c4 + 2] = k4.z; ks[r][c4 + 3] = k4.w;
        vs[r][c4] = v4.x; vs[r][c4 + 1] = v4.y; vs[r][c4 + 2] = v4.z; vs[r][c4 + 3] = v4.w;
    }
    __syncthreads();

    const float scale = 0.17677669529663689f;
    for (int e = tid; e < 2401; e += 128) {
        int i = e / 49, j = e - i * 49;
        float s = 0.f;
#pragma unroll
        for (int c = 0; c < 32; c++) s += qs[i][c] * ks[j][c];
        s *= scale;
        if (use_mask && (regn[i] != regn[j])) s -= 100.f;
        sc[i][j] = s;
    }
    __syncthreads();

    // softmax: 4 warps over rows, lanes cover columns (j = lane, lane+32)
    for (int i = wid; i < 49; i += 4) {
        float v0 = (lane < 49) ? sc[i][lane] : -1e30f;
        float v1 = (lane + 32 < 49) ? sc[i][lane + 32] : -1e30f;
        float m = fmaxf(v0, v1);
#pragma unroll
        for (int o = 16; o; o >>= 1) m = fmaxf(m, __shfl_xor_sync(0xffffffffu, m, o));
        float e0 = (lane < 49) ? __expf(v0 - m) : 0.f;
        float e1 = (lane + 32 < 49) ? __expf(v1 - m) : 0.f;
        float s = e0 + e1;
#pragma unroll
        for (int o = 16; o; o >>= 1) s += __shfl_xor_sync(0xffffffffu, s, o);
        float inv = 1.0f / s;
        if (lane < 49) sc[i][lane] = e0 * inv;
        if (lane + 32 < 49) sc[i][lane + 32] = e1 * inv;
    }
    __syncthreads();

    for (int e = tid; e < 49 * 32; e += 128) {
        int i = e >> 5, c = e & 31;
        float s = 0.f;
#pragma unroll 7
        for (int j = 0; j < 49; j++) s += sc[i][j] * vs[j][c];
        o[(size_t)tok[i] * 128 + head * 32 + c] = s;
    }
}

// ------------------------------ 2x2 patch merge + LN(512) -------------------
__global__ void __launch_bounds__(256)
merge_ln_kernel(const float* __restrict__ x, float* __restrict__ y,
                const float* __restrict__ g, const float* __restrict__ b)
{
    int warp = (blockIdx.x * blockDim.x + threadIdx.x) >> 5;
    int lane = threadIdx.x & 31;
    int bI = warp / 784;
    int r  = warp - bI * 784;
    int i  = r / 28;
    int j  = r - i * 28;
    int grp = lane >> 3;
    int hh  = grp >> 1, ww = grp & 1;
    int d0  = (lane & 7) << 4;
    const float* src =
        x + (((size_t)(bI * 56 + 2 * i + hh)) * 56 + (2 * j + ww)) * 128 + d0;

    float v[16];
#pragma unroll
    for (int t = 0; t < 4; t++) {
        float4 f = ((const float4*)src)[t];
        v[t * 4 + 0] = f.x; v[t * 4 + 1] = f.y; v[t * 4 + 2] = f.z; v[t * 4 + 3] = f.w;
    }
    float s = 0.f;
#pragma unroll
    for (int t = 0; t < 16; t++) s += v[t];
#pragma unroll
    for (int o = 16; o; o >>= 1) s += __shfl_xor_sync(0xffffffffu, s, o);
    float mean = s * (1.0f / 512.0f);
    float q = 0.f;
#pragma unroll
    for (int t = 0; t < 16; t++) { float dd = v[t] - mean; q += dd * dd; }
#pragma unroll
    for (int o = 16; o; o >>= 1) q += __shfl_xor_sync(0xffffffffu, q, o);
    float rstd = rsqrtf(q * (1.0f / 512.0f) + 1e-5f);

    int c0 = lane << 4;
    float* dst = y + (size_t)warp * 512 + c0;
#pragma unroll
    for (int t = 0; t < 4; t++) {
        float4 gg = ((const float4*)(g + c0))[t];
        float4 bb = ((const float4*)(b + c0))[t];
        float4 out;
        out.x = (v[t * 4 + 0] - mean) * rstd * gg.x + bb.x;
        out.y = (v[t * 4 + 1] - mean) * rstd * gg.y + bb.y;
        out.z = (v[t * 4 + 2] - mean) * rstd * gg.z + bb.z;
        out.w = (v[t * 4 + 3] - mean) * rstd * gg.w + bb.w;
        ((float4*)dst)[t] = out;
    }
}

// ---------------------------------------------------------------------------
extern "C" void kernel_launch(void* const* d_in, const int* in_sizes, int n_in,
                              void* d_out, int out_size)
{
    const float* x       = (const float*)d_in[0];
    const float* ln1_g   = (const float*)d_in[1];
    const float* ln1_b   = (const float*)d_in[2];
    const float* qkv_w   = (const float*)d_in[3];
    const float* qkv_b   = (const float*)d_in[4];
    const float* proj_w  = (const float*)d_in[5];
    const float* proj_b  = (const float*)d_in[6];
    const float* ln2_g   = (const float*)d_in[7];
    const float* ln2_b   = (const float*)d_in[8];
    const float* mlp_w1  = (const float*)d_in[9];
    const float* mlp_b1  = (const float*)d_in[10];
    const float* mlp_w2  = (const float*)d_in[11];
    const float* mlp_b2  = (const float*)d_in[12];
    const float* dsn_g   = (const float*)d_in[13];
    const float* dsn_b   = (const float*)d_in[14];
    const float* ds_w    = (const float*)d_in[15];
    float* out           = (float*)d_out;

    float *gx, *gh, *gq, *go, *ghid, *gds, *gwt;
    cudaGetSymbolAddress((void**)&gx,   g_x);
    cudaGetSymbolAddress((void**)&gh,   g_h);
    cudaGetSymbolAddress((void**)&gq,   g_qkv);
    cudaGetSymbolAddress((void**)&go,   g_o);
    cudaGetSymbolAddress((void**)&ghid, g_hid);
    cudaGetSymbolAddress((void**)&gds,  g_ds);
    cudaGetSymbolAddress((void**)&gwt,  g_wt);

    cudaFuncSetAttribute(gemm_mma<false, false>, cudaFuncAttributeMaxDynamicSharedMemorySize, GEMM_SMEM);
    cudaFuncSetAttribute(gemm_mma<false, true>,  cudaFuncAttributeMaxDynamicSharedMemorySize, GEMM_SMEM);
    cudaFuncSetAttribute(gemm_mma<true, false>,  cudaFuncAttributeMaxDynamicSharedMemorySize, GEMM_SMEM);

    // transposed+rounded weights: qkvT 0 (+l*49152) | projT 98304 (+l*16384) |
    // mlp1T 131072 (+l*65536) | mlp2T 262144 (+l*65536) | dsT 393216
    transpose_tf32<<<(2 * 128 * 384 + 255) / 256, 256>>>(qkv_w,  gwt + 0,      128, 384, 49152);
    transpose_tf32<<<(2 * 128 * 128 + 255) / 256, 256>>>(proj_w, gwt + 98304,  128, 128, 16384);
    transpose_tf32<<<(2 * 128 * 512 + 255) / 256, 256>>>(mlp_w1, gwt + 131072, 128, 512, 65536);
    transpose_tf32<<<(2 * 512 * 128 + 255) / 256, 256>>>(mlp_w2, gwt + 262144, 512, 128, 65536);
    transpose_tf32<<<(512 * 256 + 255) / 256, 256>>>(ds_w, gwt + 393216, 512, 256, 0);

    const int lnBlocks = TOK / 8;
    const dim3 attnGrid(4096, 4);

    for (int layer = 0; layer < 2; layer++) {
        const float* res_in = (layer == 0) ? x : gx;
        int shift   = (layer == 1) ? 3 : 0;
        int useMask = (layer == 1) ? 1 : 0;

        ln128_kernel<<<lnBlocks, 256>>>(res_in, gh,
                                        ln1_g + layer * 128, ln1_b + layer * 128);
        gemm_mma<false, false><<<dim3(3, TOK / 128), 256, GEMM_SMEM>>>(
            gh, gwt + 0 + layer * 49152, qkv_b + layer * 384, nullptr, gq, 384, 128);
        attn_kernel<<<attnGrid, 128>>>(gq, go, shift, useMask);
        gemm_mma<false, true><<<dim3(1, TOK / 128), 256, GEMM_SMEM>>>(
            go, gwt + 98304 + layer * 16384, proj_b + layer * 128, res_in, gx, 128, 128);
        ln128_kernel<<<lnBlocks, 256>>>(gx, gh,
                                        ln2_g + layer * 128, ln2_b + layer * 128);
        gemm_mma<true, false><<<dim3(4, TOK / 128), 256, GEMM_SMEM>>>(
            gh, gwt + 131072 + layer * 65536, mlp_b1 + layer * 512, nullptr, ghid, 512, 128);
        gemm_mma<false, true><<<dim3(1, TOK / 128), 256, GEMM_SMEM>>>(
            ghid, gwt + 262144 + layer * 65536, mlp_b2 + layer * 128, gx, gx, 128, 512);
    }

    merge_ln_kernel<<<DSTOK / 8, 256>>>(gx, gds, dsn_g, dsn_b);
    gemm_mma<false, false><<<dim3(2, DSTOK / 128), 256, GEMM_SMEM>>>(
        gds, gwt + 393216, nullptr, nullptr, out, 256, 512);
}